// round 4
// baseline (speedup 1.0000x reference)
#include <cuda_runtime.h>
#include <math.h>

#define NN 1024
#define HD 64
#define ER 16384
#define ESTR 68   // padded smem stride (multiple of 4 for float4 alignment)

// Scratch (allocation-free rule: __device__ globals).
// Self-cleaning state machine: all zero at module load; final_kernel returns
// everything it used to zero, so no init launch is needed.
__device__ int   g_claim[NN * NN];     // 0 = empty; claim value = edge_idx+1
__device__ float g_Q[NN * HD];
__device__ float g_K[NN * HD];
__device__ float g_V[NN * HD];
__device__ float g_SVp[16 * 64];       // per-group partial V column sums (always overwritten)
__device__ float g_acc[NN * HD];       // edge-delta value accumulator (self-reset in final)
__device__ float g_z[NN * 8];          // edge-delta normalizer (reset in final)

// ------------------------------------------------ GEMM helper (4x4 f32x2 tile)
#define GEMM_64x64_BODY(ASRC, BSRC)                                                   \
    unsigned long long acc[4][2];                                                     \
    _Pragma("unroll")                                                                 \
    for (int i = 0; i < 4; i++) { acc[i][0] = 0ULL; acc[i][1] = 0ULL; }               \
    _Pragma("unroll 16")                                                              \
    for (int k = 0; k < 64; k++) {                                                    \
        float4 av = *reinterpret_cast<const float4*>(&ASRC[k * ESTR + ty * 4]);       \
        ulonglong2 bv = *reinterpret_cast<const ulonglong2*>(&BSRC[k * 64 + tx * 4]); \
        unsigned long long ad0, ad1, ad2, ad3;                                        \
        asm("mov.b64 %0, {%1,%1};" : "=l"(ad0) : "f"(av.x));                          \
        asm("mov.b64 %0, {%1,%1};" : "=l"(ad1) : "f"(av.y));                          \
        asm("mov.b64 %0, {%1,%1};" : "=l"(ad2) : "f"(av.z));                          \
        asm("mov.b64 %0, {%1,%1};" : "=l"(ad3) : "f"(av.w));                          \
        asm("fma.rn.f32x2 %0, %1, %2, %0;" : "+l"(acc[0][0]) : "l"(ad0), "l"(bv.x));  \
        asm("fma.rn.f32x2 %0, %1, %2, %0;" : "+l"(acc[0][1]) : "l"(ad0), "l"(bv.y));  \
        asm("fma.rn.f32x2 %0, %1, %2, %0;" : "+l"(acc[1][0]) : "l"(ad1), "l"(bv.x));  \
        asm("fma.rn.f32x2 %0, %1, %2, %0;" : "+l"(acc[1][1]) : "l"(ad1), "l"(bv.y));  \
        asm("fma.rn.f32x2 %0, %1, %2, %0;" : "+l"(acc[2][0]) : "l"(ad2), "l"(bv.x));  \
        asm("fma.rn.f32x2 %0, %1, %2, %0;" : "+l"(acc[2][1]) : "l"(ad2), "l"(bv.y));  \
        asm("fma.rn.f32x2 %0, %1, %2, %0;" : "+l"(acc[3][0]) : "l"(ad3), "l"(bv.x));  \
        asm("fma.rn.f32x2 %0, %1, %2, %0;" : "+l"(acc[3][1]) : "l"(ad3), "l"(bv.y));  \
    }

// -------------------------------------------- node projections + claim pass
// blocks 0..47:  (m = b%3, node group g = b/3): [64 nodes] @ W_m -> g_{Q,K,V}
// blocks 48..63: edge claim (deterministic dedup, last duplicate wins)
__global__ void __launch_bounds__(256) proj_claim_kernel(
    const float* __restrict__ h,
    const float* __restrict__ WQ,
    const float* __restrict__ WK,
    const float* __restrict__ WV,
    const int* __restrict__ src,
    const int* __restrict__ dst) {
    int b = blockIdx.x;
    int tid = threadIdx.x;
    if (b >= 48) {
        int base = (b - 48) * 1024;
        for (int k = base + tid; k < base + 1024; k += 256) {
            int s = src[k], d = dst[k];
            if (s != d) atomicMax(&g_claim[s * NN + d], k + 1);
        }
        return;
    }
    __shared__ __align__(16) float Ws[64 * 64];     // [k][c]
    __shared__ __align__(16) float hsT[64 * ESTR];  // [k][node]
    __shared__ float sred[16 * 64];

    int m = b % 3;       // 0=Q, 1=K, 2=V
    int g = b / 3;       // node group
    int i0 = g * 64;
    const float* W = (m == 0) ? WQ : (m == 1) ? WK : WV;

    {
        float4* w4 = (float4*)Ws;
        const float4* g4 = (const float4*)W;
        for (int idx = tid; idx < 1024; idx += 256) w4[idx] = g4[idx];
    }
    {
        int el = tid >> 2, seg = tid & 3;
        const float4* gh = (const float4*)(h + (size_t)(i0 + el) * 64 + seg * 16);
#pragma unroll
        for (int q = 0; q < 4; q++) {
            float4 v = gh[q];
            int k0 = seg * 16 + q * 4;
            hsT[(k0 + 0) * ESTR + el] = v.x;
            hsT[(k0 + 1) * ESTR + el] = v.y;
            hsT[(k0 + 2) * ESTR + el] = v.z;
            hsT[(k0 + 3) * ESTR + el] = v.w;
        }
    }
    __syncthreads();

    int tx = tid & 15, ty = tid >> 4;
    GEMM_64x64_BODY(hsT, Ws)

    float* dstp = (m == 0) ? g_Q : (m == 1) ? g_K : g_V;
    float csum[4] = {0.f, 0.f, 0.f, 0.f};
#pragma unroll
    for (int i = 0; i < 4; i++) {
        float2 lo = *reinterpret_cast<float2*>(&acc[i][0]);
        float2 hi = *reinterpret_cast<float2*>(&acc[i][1]);
        float4 o = make_float4(lo.x, lo.y, hi.x, hi.y);
        *reinterpret_cast<float4*>(dstp + (size_t)(i0 + ty * 4 + i) * 64 + tx * 4) = o;
        csum[0] += o.x; csum[1] += o.y; csum[2] += o.z; csum[3] += o.w;
    }
    if (m == 2) {
        // block-local column-sum reduction -> g_SVp[g][c] (plain stores)
        *reinterpret_cast<float4*>(&sred[ty * 64 + tx * 4]) =
            make_float4(csum[0], csum[1], csum[2], csum[3]);
        __syncthreads();
        if (tid < 64) {
            float sv = 0.f;
#pragma unroll
            for (int p = 0; p < 16; p++) sv += sred[p * 64 + tid];
            g_SVp[g * 64 + tid] = sv;
        }
    }
}

// ---------------------------------------------------------------- fused edge
// Block = 64 edges. Phase 1: tiled GEMM Ehe = e_tile @ WE (f32x2 packed FMA).
// Phase 2: per-edge 3-way contraction + exp + scatter atomics.
__global__ void __launch_bounds__(256) edge_kernel(
    const float* __restrict__ e,
    const float* __restrict__ WE,
    const int* __restrict__ src,
    const int* __restrict__ dst) {
    __shared__ __align__(16) float WEs[64 * 64];     // [k][c]
    __shared__ __align__(16) float buf[64 * ESTR];   // es[k][edge], later ehe[edge][c]
    __shared__ int s_sh[64], d_sh[64];

    int tid = threadIdx.x;
    int base = blockIdx.x * 64;

    if (tid < 64) { s_sh[tid] = src[base + tid]; d_sh[tid] = dst[base + tid]; }

    {
        float4* w4 = (float4*)WEs;
        const float4* g4 = (const float4*)WE;
        for (int idx = tid; idx < 1024; idx += 256) w4[idx] = g4[idx];
    }
    {
        int el = tid >> 2, seg = tid & 3;
        const float4* ge = (const float4*)(e + (size_t)(base + el) * 64 + seg * 16);
#pragma unroll
        for (int q = 0; q < 4; q++) {
            float4 v = ge[q];
            int k0 = seg * 16 + q * 4;
            buf[(k0 + 0) * ESTR + el] = v.x;
            buf[(k0 + 1) * ESTR + el] = v.y;
            buf[(k0 + 2) * ESTR + el] = v.z;
            buf[(k0 + 3) * ESTR + el] = v.w;
        }
    }
    __syncthreads();

    // claim prefetch (independent L2 load, hidden under the GEMM below)
    int w = tid >> 5, lane = tid & 31;
    int mk = w * 8 + (lane & 7);
    int cl = g_claim[s_sh[mk] * NN + d_sh[mk]];   // 0 if empty/self-loop

    int tx = tid & 15, ty = tid >> 4;
    GEMM_64x64_BODY(buf, WEs)
    __syncthreads();  // all reads of es done before overwrite

#pragma unroll
    for (int i = 0; i < 4; i++) {
        float2 lo = *reinterpret_cast<float2*>(&acc[i][0]);
        float2 hi = *reinterpret_cast<float2*>(&acc[i][1]);
        float4 o = make_float4(lo.x, lo.y, hi.x, hi.y);
        *reinterpret_cast<float4*>(&buf[(ty * 4 + i) * ESTR + tx * 4]) = o;
    }
    __syncthreads();

    const float INVS = 0.35355339059327373f;  // 1/sqrt(8)
    const float SC   = 0.9090909090909091f;   // 1/(1+gamma)
    const float C0   = 0.09090909090909091f;  // gamma/(1+gamma)

#pragma unroll
    for (int i = 0; i < 8; i++) {
        int kl = w * 8 + i;
        int cv = __shfl_sync(0xffffffffu, cl, i);
        if (cv != base + kl + 1) continue;  // self-loop / superseded duplicate
        int s = s_sh[kl], d = d_sh[kl];
        float eh0 = buf[kl * ESTR + lane];
        float eh1 = buf[kl * ESTR + lane + 32];
        float p0 = eh0 * g_K[s * 64 + lane] * g_Q[d * 64 + lane];
        float p1 = eh1 * g_K[s * 64 + lane + 32] * g_Q[d * 64 + lane + 32];
#pragma unroll
        for (int off = 4; off; off >>= 1) {
            p0 += __shfl_xor_sync(0xffffffffu, p0, off);
            p1 += __shfl_xor_sync(0xffffffffu, p1, off);
        }
        float d0 = expf(fminf(fmaxf(p0 * INVS, -5.f), 5.f)) * SC - C0;
        float d1 = expf(fminf(fmaxf(p1 * INVS, -5.f), 5.f)) * SC - C0;
        atomicAdd(&g_acc[d * 64 + lane],      d0 * g_V[s * 64 + lane]);
        atomicAdd(&g_acc[d * 64 + lane + 32], d1 * g_V[s * 64 + lane + 32]);
        if ((lane & 7) == 0) {
            atomicAdd(&g_z[d * 8 + (lane >> 3)],     d0);
            atomicAdd(&g_z[d * 8 + 4 + (lane >> 3)], d1);
        }
    }
}

// --------------------------------------------------- finalize + state reset
// blocks 0..63: normalize output (16 node-rows each) and reset g_acc/g_z.
// blocks 64..79: reset the touched claim-map entries (64 KB instead of 4 MB).
__global__ void __launch_bounds__(256) final_kernel(
    float* __restrict__ out,
    const int* __restrict__ src,
    const int* __restrict__ dst) {
    int b = blockIdx.x;
    int tid = threadIdx.x;
    if (b >= 64) {
        int base = (b - 64) * 1024;
        for (int k = base + tid; k < base + 1024; k += 256) {
            int s = src[k], d = dst[k];
            if (s != d) g_claim[s * NN + d] = 0;   // benign dup-write race (same value)
        }
        return;
    }
    const float C0 = 0.09090909090909091f;

    __shared__ float svs[64];
    if (tid < 64) {
        float sv = 0.f;
#pragma unroll
        for (int p = 0; p < 16; p++) sv += g_SVp[p * 64 + tid];
        svs[tid] = sv;
    }
    __syncthreads();

    // block handles node rows 16b .. 16b+15 (1024 floats = 256 float4)
    int idx4 = b * 256 + tid;
    int idx = idx4 * 4;
    int j = idx >> 6;
    int c0 = idx & 63;          // multiple of 4 -> all 4 lanes share a head
    int hh = c0 >> 3;
    float z = C0 * 1023.0f + g_z[j * 8 + hh] + 1e-6f;
    float rz = 1.0f / z;
    float4 a = ((const float4*)g_acc)[idx4];
    float4 v = ((const float4*)g_V)[idx4];
    float4 o;
    o.x = (C0 * (svs[c0 + 0] - v.x) + a.x) * rz;
    o.y = (C0 * (svs[c0 + 1] - v.y) + a.y) * rz;
    o.z = (C0 * (svs[c0 + 2] - v.z) + a.z) * rz;
    o.w = (C0 * (svs[c0 + 3] - v.w) + a.w) * rz;
    ((float4*)out)[idx4] = o;
    ((float4*)g_acc)[idx4] = make_float4(0.f, 0.f, 0.f, 0.f);  // self-reset

    __syncthreads();  // all g_z reads in this block done
    if (tid < 128) g_z[b * 128 + tid] = 0.f;  // reset this block's 16 rows x 8 heads
}

extern "C" void kernel_launch(void* const* d_in, const int* in_sizes, int n_in,
                              void* d_out, int out_size) {
    const float* h  = (const float*)d_in[0];
    const float* e  = (const float*)d_in[1];
    const float* WQ = (const float*)d_in[2];
    const float* WK = (const float*)d_in[3];
    const float* WE = (const float*)d_in[4];
    // d_in[5..7] = WQ2, WK2, WE2: unobservable (fake weights survive only
    // off-edge, where they equal the constant gamma/(1+gamma)).
    const float* WV = (const float*)d_in[8];
    const int* rs   = (const int*)d_in[9];
    const int* rd   = (const int*)d_in[10];
    float* out = (float*)d_out;

    proj_claim_kernel<<<64, 256>>>(h, WQ, WK, WV, rs, rd);
    edge_kernel<<<256, 256>>>(e, WE, rs, rd);
    final_kernel<<<80, 256>>>(out, rs, rd);
}